// round 1
// baseline (speedup 1.0000x reference)
#include <cuda_runtime.h>

#define HD 128
#define TM 64
#define NT 256
#define MAXN 100000

// scatter-add scratch: agg[N][128]
__device__ float g_agg[(size_t)MAXN * HD];

__global__ void zero_agg_kernel(int n4) {
    int i = blockIdx.x * blockDim.x + threadIdx.x;
    float4 z = make_float4(0.f, 0.f, 0.f, 0.f);
    for (; i < n4; i += gridDim.x * blockDim.x)
        ((float4*)g_agg)[i] = z;
}

// One dense layer on a 64-row tile: sY[64][128] = act(sX[64][K] @ W[K][128] + b)
// Thread layout: ty = warp (8 rows each), tx = lane (4 consecutive cols each).
__device__ __forceinline__ void gemm_layer(
    const float* __restrict__ W, const float* __restrict__ bias,
    const float* sX, int ldx, float* sW, float* sY, int K, bool relu,
    int tid, int tx, int ty)
{
    float acc[8][4];
#pragma unroll
    for (int i = 0; i < 8; i++) {
        acc[i][0] = 0.f; acc[i][1] = 0.f; acc[i][2] = 0.f; acc[i][3] = 0.f;
    }
    for (int kt = 0; kt < K; kt += 16) {
        __syncthreads();
        // stage W[kt:kt+16][0:128] (2048 floats = 512 float4)
#pragma unroll
        for (int t = tid; t < 512; t += NT)
            ((float4*)sW)[t] = ((const float4*)(W + (size_t)kt * HD))[t];
        __syncthreads();
#pragma unroll
        for (int kk = 0; kk < 16; kk++) {
            float4 w = *(const float4*)(sW + kk * HD + tx * 4);
#pragma unroll
            for (int i = 0; i < 8; i++) {
                float a = sX[(ty * 8 + i) * ldx + kt + kk];
                acc[i][0] = fmaf(a, w.x, acc[i][0]);
                acc[i][1] = fmaf(a, w.y, acc[i][1]);
                acc[i][2] = fmaf(a, w.z, acc[i][2]);
                acc[i][3] = fmaf(a, w.w, acc[i][3]);
            }
        }
    }
    float4 bb = *(const float4*)(bias + tx * 4);
#pragma unroll
    for (int i = 0; i < 8; i++) {
        float4 o;
        o.x = acc[i][0] + bb.x; o.y = acc[i][1] + bb.y;
        o.z = acc[i][2] + bb.z; o.w = acc[i][3] + bb.w;
        if (relu) {
            o.x = fmaxf(o.x, 0.f); o.y = fmaxf(o.y, 0.f);
            o.z = fmaxf(o.z, 0.f); o.w = fmaxf(o.w, 0.f);
        }
        *(float4*)(sY + (ty * 8 + i) * HD + tx * 4) = o;
    }
}

// Edge block: gather [na[s] | na[r] | ea] -> 4-layer MLP -> LN -> (out_edge += ea, scatter to agg)
__global__ void edge_kernel(
    const float* __restrict__ node_attr, const float* __restrict__ edge_attr,
    const int* __restrict__ senders, const int* __restrict__ receivers,
    const float* __restrict__ w0, const float* __restrict__ b0,
    const float* __restrict__ w1, const float* __restrict__ b1,
    const float* __restrict__ w2, const float* __restrict__ b2,
    const float* __restrict__ w3, const float* __restrict__ b3,
    const float* __restrict__ gvec, const float* __restrict__ bvec,
    float* __restrict__ out_edge, int E)
{
    extern __shared__ float smem[];
    float* sIn = smem;                  // 64*384
    float* sW  = smem + TM * 384;       // 16*128
    float* sB  = sW + 16 * HD;          // 64*128 (buffer B)
    float* sA  = sIn;                   // buffer A aliases front of sIn (64*128)

    int tid = threadIdx.x, tx = tid & 31, ty = tid >> 5;
    long base = (long)blockIdx.x * TM;

    // gather: 64 rows x 3 segments, one warp per row-segment, float4 per lane
    for (int task = ty; task < TM * 3; task += 8) {
        int r = task / 3, sgm = task - r * 3;
        long e = base + r; if (e >= E) e = E - 1;
        const float* src;
        if (sgm == 0)      src = node_attr + (size_t)senders[e] * HD;
        else if (sgm == 1) src = node_attr + (size_t)receivers[e] * HD;
        else               src = edge_attr + (size_t)e * HD;
        ((float4*)(sIn + r * 384 + sgm * HD))[tx] = ((const float4*)src)[tx];
    }

    gemm_layer(w0, b0, sIn, 384, sW, sB, 384, true,  tid, tx, ty);
    gemm_layer(w1, b1, sB,  HD,  sW, sA, HD,  true,  tid, tx, ty);
    gemm_layer(w2, b2, sA,  HD,  sW, sB, HD,  true,  tid, tx, ty);
    gemm_layer(w3, b3, sB,  HD,  sW, sA, HD,  false, tid, tx, ty);
    __syncthreads();

    // LayerNorm: 4 threads per row, 32 elems each; quad reduce via shfl
    int r = tid >> 2, seg = tid & 3;
    const float* row = sA + r * HD + seg * 32;
    float s = 0.f, s2 = 0.f;
#pragma unroll
    for (int i = 0; i < 32; i++) { float x = row[i]; s += x; s2 = fmaf(x, x, s2); }
    s  += __shfl_xor_sync(0xffffffffu, s, 1);
    s  += __shfl_xor_sync(0xffffffffu, s, 2);
    s2 += __shfl_xor_sync(0xffffffffu, s2, 1);
    s2 += __shfl_xor_sync(0xffffffffu, s2, 2);
    float m   = s * (1.0f / HD);
    float var = fmaxf(s2 * (1.0f / HD) - m * m, 0.f);
    float rs  = rsqrtf(var + 1e-5f);

    long e = base + r;
    if (e < E) {
        int rv = receivers[e];
        float* aggrow = g_agg + (size_t)rv * HD;
        const float4* ea4 = (const float4*)(edge_attr + (size_t)e * HD);
        float4* oe4 = (float4*)(out_edge + (size_t)e * HD);
#pragma unroll
        for (int q = 0; q < 8; q++) {
            int h = seg * 32 + q * 4;
            float4 x4 = *(const float4*)(row + q * 4);
            float4 g4 = *(const float4*)(gvec + h);
            float4 t4 = *(const float4*)(bvec + h);
            float4 ln;
            ln.x = (x4.x - m) * rs * g4.x + t4.x;
            ln.y = (x4.y - m) * rs * g4.y + t4.y;
            ln.z = (x4.z - m) * rs * g4.z + t4.z;
            ln.w = (x4.w - m) * rs * g4.w + t4.w;
            float4 eav = ea4[seg * 8 + q];
            float4 ov = make_float4(ln.x + eav.x, ln.y + eav.y, ln.z + eav.z, ln.w + eav.w);
            oe4[seg * 8 + q] = ov;
            atomicAdd(aggrow + h + 0, ln.x);
            atomicAdd(aggrow + h + 1, ln.y);
            atomicAdd(aggrow + h + 2, ln.z);
            atomicAdd(aggrow + h + 3, ln.w);
        }
    }
}

// Node block: [na | agg] -> 4-layer MLP -> LN -> out_node += na
__global__ void node_kernel(
    const float* __restrict__ node_attr,
    const float* __restrict__ w0, const float* __restrict__ b0,
    const float* __restrict__ w1, const float* __restrict__ b1,
    const float* __restrict__ w2, const float* __restrict__ b2,
    const float* __restrict__ w3, const float* __restrict__ b3,
    const float* __restrict__ gvec, const float* __restrict__ bvec,
    float* __restrict__ out_node, int N)
{
    extern __shared__ float smem[];
    float* sIn = smem;                  // 64*256
    float* sW  = smem + TM * 256;       // 16*128
    float* sB  = sW + 16 * HD;          // 64*128
    float* sA  = sIn;

    int tid = threadIdx.x, tx = tid & 31, ty = tid >> 5;
    long base = (long)blockIdx.x * TM;

    for (int task = ty; task < TM * 2; task += 8) {
        int r = task >> 1, sgm = task & 1;
        long n = base + r; if (n >= N) n = N - 1;
        const float* src = (sgm == 0) ? node_attr + (size_t)n * HD
                                      : g_agg + (size_t)n * HD;
        ((float4*)(sIn + r * 256 + sgm * HD))[tx] = ((const float4*)src)[tx];
    }

    gemm_layer(w0, b0, sIn, 256, sW, sB, 256, true,  tid, tx, ty);
    gemm_layer(w1, b1, sB,  HD,  sW, sA, HD,  true,  tid, tx, ty);
    gemm_layer(w2, b2, sA,  HD,  sW, sB, HD,  true,  tid, tx, ty);
    gemm_layer(w3, b3, sB,  HD,  sW, sA, HD,  false, tid, tx, ty);
    __syncthreads();

    int r = tid >> 2, seg = tid & 3;
    const float* row = sA + r * HD + seg * 32;
    float s = 0.f, s2 = 0.f;
#pragma unroll
    for (int i = 0; i < 32; i++) { float x = row[i]; s += x; s2 = fmaf(x, x, s2); }
    s  += __shfl_xor_sync(0xffffffffu, s, 1);
    s  += __shfl_xor_sync(0xffffffffu, s, 2);
    s2 += __shfl_xor_sync(0xffffffffu, s2, 1);
    s2 += __shfl_xor_sync(0xffffffffu, s2, 2);
    float m   = s * (1.0f / HD);
    float var = fmaxf(s2 * (1.0f / HD) - m * m, 0.f);
    float rs  = rsqrtf(var + 1e-5f);

    long n = base + r;
    if (n < N) {
        const float4* na4 = (const float4*)(node_attr + (size_t)n * HD);
        float4* on4 = (float4*)(out_node + (size_t)n * HD);
#pragma unroll
        for (int q = 0; q < 8; q++) {
            int h = seg * 32 + q * 4;
            float4 x4 = *(const float4*)(row + q * 4);
            float4 g4 = *(const float4*)(gvec + h);
            float4 t4 = *(const float4*)(bvec + h);
            float4 nav = na4[seg * 8 + q];
            float4 ov;
            ov.x = (x4.x - m) * rs * g4.x + t4.x + nav.x;
            ov.y = (x4.y - m) * rs * g4.y + t4.y + nav.y;
            ov.z = (x4.z - m) * rs * g4.z + t4.z + nav.z;
            ov.w = (x4.w - m) * rs * g4.w + t4.w + nav.w;
            on4[seg * 8 + q] = ov;
        }
    }
}

extern "C" void kernel_launch(void* const* d_in, const int* in_sizes, int n_in,
                              void* d_out, int out_size)
{
    const float* node_attr = (const float*)d_in[0];
    const float* edge_attr = (const float*)d_in[1];
    const int*   ei        = (const int*)d_in[2];
    // d_in[3] = num_nodes (scalar, unused; derive from sizes)
    const float* ew0 = (const float*)d_in[4];  const float* eb0 = (const float*)d_in[5];
    const float* ew1 = (const float*)d_in[6];  const float* eb1 = (const float*)d_in[7];
    const float* ew2 = (const float*)d_in[8];  const float* eb2 = (const float*)d_in[9];
    const float* ew3 = (const float*)d_in[10]; const float* eb3 = (const float*)d_in[11];
    const float* eg  = (const float*)d_in[12]; const float* ebt = (const float*)d_in[13];
    const float* nw0 = (const float*)d_in[14]; const float* nb0 = (const float*)d_in[15];
    const float* nw1 = (const float*)d_in[16]; const float* nb1 = (const float*)d_in[17];
    const float* nw2 = (const float*)d_in[18]; const float* nb2 = (const float*)d_in[19];
    const float* nw3 = (const float*)d_in[20]; const float* nb3 = (const float*)d_in[21];
    const float* ng  = (const float*)d_in[22]; const float* nbt = (const float*)d_in[23];

    int N = in_sizes[0] / HD;
    int E = in_sizes[1] / HD;

    float* out_node = (float*)d_out;
    float* out_edge = out_node + (size_t)N * HD;

    const int SMEM_E = (TM * 384 + 16 * HD + TM * HD) * sizeof(float);  // 139264
    const int SMEM_N = (TM * 256 + 16 * HD + TM * HD) * sizeof(float);  // 106496
    cudaFuncSetAttribute(edge_kernel, cudaFuncAttributeMaxDynamicSharedMemorySize, SMEM_E);
    cudaFuncSetAttribute(node_kernel, cudaFuncAttributeMaxDynamicSharedMemorySize, SMEM_N);

    zero_agg_kernel<<<1024, 256>>>(N * HD / 4);

    const int* senders   = ei;
    const int* receivers = ei + E;

    edge_kernel<<<(E + TM - 1) / TM, NT, SMEM_E>>>(
        node_attr, edge_attr, senders, receivers,
        ew0, eb0, ew1, eb1, ew2, eb2, ew3, eb3, eg, ebt,
        out_edge, E);

    node_kernel<<<(N + TM - 1) / TM, NT, SMEM_N>>>(
        node_attr,
        nw0, nb0, nw1, nb1, nw2, nb2, nw3, nb3, ng, nbt,
        out_node, N);
}

// round 6
// speedup vs baseline: 3.1693x; 3.1693x over previous
#include <cuda_runtime.h>
#include <cstdint>

#define HD 128
#define MT 128
#define NT 256
#define MAXN 100000
#define FB_TM 64

#if !defined(__CUDA_ARCH__) || defined(__CUDA_ARCH_FEAT_SM103_ALL)
#define HAS_TC 1
#else
#define HAS_TC 0
#endif

__device__ float g_agg[(size_t)MAXN * HD];
__device__ unsigned char g_wimg[11 * 65536];

// ---------------- helpers ----------------
__device__ __forceinline__ uint32_t smem_u32(const void* p) {
    uint32_t a;
    asm("{ .reg .u64 t; cvta.to.shared.u64 t, %1; cvt.u32.u64 %0, t; }" : "=r"(a) : "l"(p));
    return a;
}

#if HAS_TC
__device__ __forceinline__ uint32_t elect1() {
    uint32_t p;
    asm volatile("{ .reg .pred p; elect.sync _|p, 0xFFFFFFFF; selp.b32 %0, 1, 0, p; }" : "=r"(p));
    return p;
}

#define TC_ALLOC(slot, n) asm volatile("tcgen05.alloc.cta_group::1.sync.aligned.shared::cta.b32 [%0], %1;" :: "r"(slot), "r"(n) : "memory")
#define TC_RELINQ()       asm volatile("tcgen05.relinquish_alloc_permit.cta_group::1.sync.aligned;")
#define TC_DEALLOC(t, n)  asm volatile("tcgen05.dealloc.cta_group::1.sync.aligned.b32 %0, %1;" :: "r"(t), "r"(n))
#define TC_COMMIT(mb)     asm volatile("tcgen05.commit.cta_group::1.mbarrier::arrive::one.shared::cluster.b64 [%0];" :: "r"(mb) : "memory")
#define TC_WAIT_LD()      asm volatile("tcgen05.wait::ld.sync.aligned;" ::: "memory")
#define TC_WAIT_ST()      asm volatile("tcgen05.wait::st.sync.aligned;" ::: "memory")
#define TC_FENCE_BEFORE() asm volatile("tcgen05.fence::before_thread_sync;" ::: "memory")
#define TC_FENCE_AFTER()  asm volatile("tcgen05.fence::after_thread_sync;" ::: "memory")
#define FENCE_ASYNC()     asm volatile("fence.proxy.async.shared::cta;" ::: "memory")
#define MBAR_INIT(mb, c)  asm volatile("mbarrier.init.shared.b64 [%0], %1;" :: "r"(mb), "r"(c) : "memory")
#define MBAR_INVAL(mb)    asm volatile("mbarrier.inval.shared.b64 [%0];" :: "r"(mb) : "memory")

#define MBAR_WAIT(mbar, phase) do { \
    uint32_t _mb = (mbar), _ph = (phase), _done; \
    asm volatile("{\n\t.reg .pred p;\n\t" \
        "mbarrier.try_wait.parity.acquire.cta.shared::cta.b64 p, [%1], %2;\n\t" \
        "selp.b32 %0, 1, 0, p;\n\t}" : "=r"(_done) : "r"(_mb), "r"(_ph) : "memory"); \
    if (!_done) { \
        asm volatile("{\n\t.reg .pred P1;\n\t" \
            "WL_%=:\n\t" \
            "mbarrier.try_wait.parity.acquire.cta.shared::cta.b64 P1, [%0], %1, 0x989680;\n\t" \
            "@P1 bra.uni WD_%=;\n\t" \
            "bra.uni WL_%=;\n\t" \
            "WD_%=:\n\t}" :: "r"(_mb), "r"(_ph) : "memory"); \
    } \
} while (0)

#define LD32(r, addr) \
    asm volatile("tcgen05.ld.sync.aligned.32x32b.x32.b32 " \
        "{%0, %1, %2, %3, %4, %5, %6, %7, " \
        " %8, %9, %10, %11, %12, %13, %14, %15, " \
        " %16, %17, %18, %19, %20, %21, %22, %23, " \
        " %24, %25, %26, %27, %28, %29, %30, %31}, [%32];" \
        : "=r"((r)[0]),  "=r"((r)[1]),  "=r"((r)[2]),  "=r"((r)[3]), \
          "=r"((r)[4]),  "=r"((r)[5]),  "=r"((r)[6]),  "=r"((r)[7]), \
          "=r"((r)[8]),  "=r"((r)[9]),  "=r"((r)[10]), "=r"((r)[11]), \
          "=r"((r)[12]), "=r"((r)[13]), "=r"((r)[14]), "=r"((r)[15]), \
          "=r"((r)[16]), "=r"((r)[17]), "=r"((r)[18]), "=r"((r)[19]), \
          "=r"((r)[20]), "=r"((r)[21]), "=r"((r)[22]), "=r"((r)[23]), \
          "=r"((r)[24]), "=r"((r)[25]), "=r"((r)[26]), "=r"((r)[27]), \
          "=r"((r)[28]), "=r"((r)[29]), "=r"((r)[30]), "=r"((r)[31]) \
        : "r"(addr))

#define ST16(addr, r) \
    asm volatile("tcgen05.st.sync.aligned.32x32b.x16.b32 [%0], " \
        "{%1, %2, %3, %4, %5, %6, %7, %8, " \
        " %9, %10, %11, %12, %13, %14, %15, %16};" \
        :: "r"(addr), \
           "r"((r)[0]),  "r"((r)[1]),  "r"((r)[2]),  "r"((r)[3]), \
           "r"((r)[4]),  "r"((r)[5]),  "r"((r)[6]),  "r"((r)[7]), \
           "r"((r)[8]),  "r"((r)[9]),  "r"((r)[10]), "r"((r)[11]), \
           "r"((r)[12]), "r"((r)[13]), "r"((r)[14]), "r"((r)[15]) \
        : "memory")
#endif  // HAS_TC

// test_mma_iter B layout: N=32 tile, K=128, blocked atoms (4 atom-rows x 2 atom-cols)
__device__ __host__ __forceinline__ uint32_t b_off32(int row, int col) {
    uint32_t off = ((uint32_t)(row >> 3) + (uint32_t)(col >> 6) * 4u) * 1024u
                 + (uint32_t)(row & 7) * 128u + (uint32_t)(col & 63) * 2u;
    return off ^ ((off >> 3) & 0x70u);
}

__device__ __forceinline__ uint64_t mk_desc(uint32_t a) {
    return ((uint64_t)2 << 61) | ((uint64_t)1 << 46) | ((uint64_t)64 << 32)
         | ((uint64_t)1 << 16) | ((uint64_t)(a >> 4) & 0x3FFF);
}

// ---------------- weight prep (arch-generic) ----------------
// image layout: [tile0..3 hi (4 x 8KB)] [tile0..3 lo (4 x 8KB)] = 64KB
__global__ void prep_w_kernel(const float* __restrict__ W, int kbase, int img) {
    int idx = blockIdx.x * blockDim.x + threadIdx.x;
    if (idx >= 128 * 128) return;
    int n = idx >> 7, k = idx & 127;
    float x = W[(size_t)(kbase + k) * HD + n];
    uint32_t xb = __float_as_uint(x);
    uint32_t hb = (xb + 0x7FFFu + ((xb >> 16) & 1u)) & 0xFFFF0000u;
    float lo = x - __uint_as_float(hb);
    uint32_t lb = __float_as_uint(lo);
    uint32_t l16 = ((lb + 0x7FFFu + ((lb >> 16) & 1u)) >> 16) & 0xFFFFu;
    int tile = n >> 5, r32 = n & 31;
    uint32_t off = b_off32(r32, k);
    unsigned char* base = g_wimg + (size_t)img * 65536 + (size_t)tile * 8192;
    *(uint16_t*)(base + off)         = (uint16_t)(hb >> 16);
    *(uint16_t*)(base + 32768 + off) = (uint16_t)l16;
}

__global__ void zero_agg_kernel(int n4) {
    int i = blockIdx.x * blockDim.x + threadIdx.x;
    float4 z = make_float4(0.f, 0.f, 0.f, 0.f);
    for (; i < n4; i += gridDim.x * blockDim.x)
        ((float4*)g_agg)[i] = z;
}

// ---------------- fallback GEMM (arch-generic, R1-proven) ----------------
__device__ __forceinline__ void fb_gemm(
    const float* __restrict__ W, const float* __restrict__ bias,
    const float* sX, int ldx, float* sW, float* sY, int K, bool relu,
    int tid, int tx, int ty)
{
    float acc[8][4];
#pragma unroll
    for (int i = 0; i < 8; i++) {
        acc[i][0] = 0.f; acc[i][1] = 0.f; acc[i][2] = 0.f; acc[i][3] = 0.f;
    }
    for (int kt = 0; kt < K; kt += 16) {
        __syncthreads();
        for (int t = tid; t < 512; t += NT)
            ((float4*)sW)[t] = ((const float4*)(W + (size_t)kt * HD))[t];
        __syncthreads();
#pragma unroll
        for (int kk = 0; kk < 16; kk++) {
            float4 w = *(const float4*)(sW + kk * HD + tx * 4);
#pragma unroll
            for (int i = 0; i < 8; i++) {
                float a = sX[(ty * 8 + i) * ldx + kt + kk];
                acc[i][0] = fmaf(a, w.x, acc[i][0]);
                acc[i][1] = fmaf(a, w.y, acc[i][1]);
                acc[i][2] = fmaf(a, w.z, acc[i][2]);
                acc[i][3] = fmaf(a, w.w, acc[i][3]);
            }
        }
    }
    float4 bb = *(const float4*)(bias + tx * 4);
#pragma unroll
    for (int i = 0; i < 8; i++) {
        float4 o;
        o.x = acc[i][0] + bb.x; o.y = acc[i][1] + bb.y;
        o.z = acc[i][2] + bb.z; o.w = acc[i][3] + bb.w;
        if (relu) {
            o.x = fmaxf(o.x, 0.f); o.y = fmaxf(o.y, 0.f);
            o.z = fmaxf(o.z, 0.f); o.w = fmaxf(o.w, 0.f);
        }
        *(float4*)(sY + (ty * 8 + i) * HD + tx * 4) = o;
    }
}

#if HAS_TC
// ---------------- tcgen05 device pieces ----------------
// TMEM columns: A_hi 0-63, A_lo 64-127, D 128-255.
#define A_LO_COL 64
#define D_COL    128

__device__ __forceinline__ void split2(float x0, float x1, uint32_t& h, uint32_t& l) {
    uint32_t b0 = __float_as_uint(x0), b1 = __float_as_uint(x1);
    uint32_t h0 = (b0 + 0x7FFFu + ((b0 >> 16) & 1u)) & 0xFFFF0000u;
    uint32_t h1 = (b1 + 0x7FFFu + ((b1 >> 16) & 1u)) & 0xFFFF0000u;
    h = (h0 >> 16) | h1;
    float l0 = x0 - __uint_as_float(h0);
    float l1 = x1 - __uint_as_float(h1);
    asm("cvt.rn.bf16x2.f32 %0, %1, %2;" : "=r"(l) : "f"(l1), "f"(l0));
}

// WG0 thread: full 128-float gmem row -> TMEM A (64 hi + 64 lo cols), chunked.
__device__ __forceinline__ void gm_row_to_A(const float* p, uint32_t dT, uint32_t woff) {
#pragma unroll
    for (int c = 0; c < 4; c++) {
        uint32_t hi[16], lo[16];
#pragma unroll
        for (int i = 0; i < 8; i++) {
            float4 v = ((const float4*)p)[c * 8 + i];
            split2(v.x, v.y, hi[2 * i], lo[2 * i]);
            split2(v.z, v.w, hi[2 * i + 1], lo[2 * i + 1]);
        }
        ST16(dT + c * 16 + woff, hi);
        ST16(dT + A_LO_COL + c * 16 + woff, lo);
    }
    TC_WAIT_ST();
}

// WG0 thread: D row (+bias, relu) -> TMEM A, chunked (one warp per subpartition).
__device__ __forceinline__ void d_row_to_A(uint32_t dT, const float* bias, uint32_t woff) {
#pragma unroll
    for (int c = 0; c < 4; c++) {
        uint32_t d[32];
        LD32(d, dT + D_COL + c * 32 + woff);
        TC_WAIT_LD();
        uint32_t hi[16], lo[16];
#pragma unroll
        for (int m = 0; m < 16; m++) {
            float x0 = fmaxf(__uint_as_float(d[2 * m]) + bias[c * 32 + 2 * m], 0.f);
            float x1 = fmaxf(__uint_as_float(d[2 * m + 1]) + bias[c * 32 + 2 * m + 1], 0.f);
            split2(x0, x1, hi[m], lo[m]);
        }
        ST16(dT + c * 16 + woff, hi);
        ST16(dT + A_LO_COL + c * 16 + woff, lo);
    }
    TC_WAIT_ST();
}

// WG1: copy one 64KB weight image to smem (128 threads x 32 uint4)
__device__ __forceinline__ void copy_wimg(int img, uint4* wdst, int wtid) {
    const uint4* src = (const uint4*)(g_wimg + (size_t)img * 65536);
#pragma unroll
    for (int it = 0; it < 32; it++) {
        int t = wtid + it * 128;
        wdst[t] = src[t];
    }
}

// 96 dispatches: 4 N=32 tiles x 3 split terms x 8 K=16 steps. Validated TS form.
__device__ __forceinline__ void dispatch_mma(uint32_t dT, uint32_t wsm, bool first) {
    const uint32_t idesc = 0x8080490u;  // verbatim test_mma/test_mma_iter
    uint32_t z = 0;
#pragma unroll
    for (int tile = 0; tile < 4; tile++) {
        uint32_t d = dT + D_COL + tile * 32;
#pragma unroll
        for (int term = 0; term < 3; term++) {
            uint32_t a_base = dT + (term == 1 ? A_LO_COL : 0);
            uint64_t bd = mk_desc(wsm + (term == 2 ? 32768u : 0u) + tile * 8192u);
#pragma unroll
            for (int ks = 0; ks < 8; ks++) {
                uint32_t a = a_base + ks * 8;
                uint64_t b = bd + (uint64_t)((ks & 3) * 2 + (ks >> 2) * 256);  // test_mma_iter offsets
                uint32_t en = (first && term == 0 && ks == 0) ? 0u : 1u;
                asm volatile("{\n\t.reg .pred p;\n\tsetp.ne.u32 p, %5, 0;\n\t"
                    "tcgen05.mma.cta_group::1.kind::f16 [%0], [%1], %2, %3, {%4, %4, %4, %4}, p;\n\t}"
                    :: "r"(d), "r"(a), "l"(b), "r"(idesc), "r"(z), "r"(en)
                    : "memory");
            }
        }
    }
}
#endif  // HAS_TC

// smem layout (1024-aligned base)
#define OFF_W    0
#define OFF_BIAS 65536
#define OFF_G    67584
#define OFF_BT   68096
#define OFF_TM   68608
#define OFF_MBAR 68616
#define SMEM_SZ  139264   // = fallback edge requirement; forces occupancy 1 (no TMEM alloc contention)

// ---------------- edge kernel ----------------
__global__ void __launch_bounds__(NT, 1) __cluster_dims__(1, 1, 1) edge_kernel(
    const float* __restrict__ node_attr, const float* __restrict__ edge_attr,
    const int* __restrict__ senders, const int* __restrict__ receivers,
    const float* __restrict__ w0, const float* __restrict__ w1,
    const float* __restrict__ w2, const float* __restrict__ w3,
    const float* __restrict__ eb0, const float* __restrict__ eb1,
    const float* __restrict__ eb2, const float* __restrict__ eb3,
    const float* __restrict__ eg, const float* __restrict__ ebt,
    float* __restrict__ out_edge, int E)
{
    extern __shared__ uint8_t smraw[];
#if HAS_TC
    uint32_t sb = smem_u32(smraw);
    uint32_t sbase = (sb + 1023) & ~1023u;
    uint8_t* sm = smraw + (sbase - sb);
    float* sBias = (float*)(sm + OFF_BIAS);
    float* sG    = (float*)(sm + OFF_G);
    float* sBt   = (float*)(sm + OFF_BT);
    uint32_t* sTm = (uint32_t*)(sm + OFF_TM);
    uint32_t mbar = sbase + OFF_MBAR;

    int tid = threadIdx.x;
    int wid = tid >> 5;
    bool wg0 = (wid < 4);
    int wg_tid = tid & 127;
    uint32_t woff = ((uint32_t)(wg_tid >> 5)) << 21;  // == warp id within wg0; matches SMSP
    long base = (long)blockIdx.x * MT;
    long e = base + wg_tid;               // WG0 thread's row
    long ec = (e < E) ? e : (long)(E - 1);

    if (wid == 0) TC_ALLOC(sbase + OFF_TM, 512);
    else TC_RELINQ();
    if (tid == 0) MBAR_INIT(mbar, 1);
    if (tid < 128) {
        sBias[tid] = eb0[tid]; sBias[128 + tid] = eb1[tid];
        sBias[256 + tid] = eb2[tid]; sBias[384 + tid] = eb3[tid];
        sG[tid] = eg[tid]; sBt[tid] = ebt[tid];
    }
    __syncthreads();
    uint32_t dT = *sTm;

    int phase = 0;
    for (int step = 0; step < 6; step++) {
        if (wg0) {
            if (step < 3) {
                const float* src;
                if (step == 0)      src = node_attr + (size_t)senders[ec] * HD;
                else if (step == 1) src = node_attr + (size_t)receivers[ec] * HD;
                else                src = edge_attr + (size_t)ec * HD;
                gm_row_to_A(src, dT, woff);
            } else {
                d_row_to_A(dT, sBias + (step - 3) * 128, woff);
            }
            TC_FENCE_BEFORE();
        } else {
            copy_wimg(step, (uint4*)(sm + OFF_W), wg_tid);
            FENCE_ASYNC();
        }
        __syncthreads();
        if (wid == 0) {
            if (elect1()) {
                TC_FENCE_AFTER();
                dispatch_mma(dT, sbase + OFF_W, (step == 0 || step >= 3));
                TC_COMMIT(mbar);
            }
        }
        MBAR_WAIT(mbar, phase);
        phase ^= 1;
        TC_FENCE_AFTER();
    }

    // ---- LayerNorm + residual + scatter (WG0 only; one full row per thread) ----
    if (wg0) {
        float s = 0.f, s2 = 0.f;
#pragma unroll
        for (int c = 0; c < 4; c++) {
            uint32_t d[32];
            LD32(d, dT + D_COL + c * 32 + woff);
            TC_WAIT_LD();
#pragma unroll
            for (int i = 0; i < 32; i++) {
                float x = __uint_as_float(d[i]) + sBias[384 + c * 32 + i];
                s += x; s2 = fmaf(x, x, s2);
            }
        }
        float m   = s * (1.0f / HD);
        float var = fmaxf(s2 * (1.0f / HD) - m * m, 0.f);
        float rs  = rsqrtf(var + 1e-5f);

        int rv = (e < E) ? receivers[e] : 0;
        const float* ea = edge_attr + (size_t)ec * HD;
        float* oe = out_edge + (size_t)ec * HD;
        float* aggrow = g_agg + (size_t)rv * HD;

#pragma unroll
        for (int c = 0; c < 4; c++) {
            uint32_t d[32];
            LD32(d, dT + D_COL + c * 32 + woff);
            TC_WAIT_LD();
            if (e < E) {
#pragma unroll
                for (int g = 0; g < 8; g++) {
                    int col = c * 32 + g * 4;
                    float l0 = (__uint_as_float(d[g*4+0]) + sBias[384+col+0] - m) * rs * sG[col+0] + sBt[col+0];
                    float l1 = (__uint_as_float(d[g*4+1]) + sBias[384+col+1] - m) * rs * sG[col+1] + sBt[col+1];
                    float l2 = (__uint_as_float(d[g*4+2]) + sBias[384+col+2] - m) * rs * sG[col+2] + sBt[col+2];
                    float l3 = (__uint_as_float(d[g*4+3]) + sBias[384+col+3] - m) * rs * sG[col+3] + sBt[col+3];
                    float4 ev = *(const float4*)(ea + col);
                    *(float4*)(oe + col) = make_float4(l0 + ev.x, l1 + ev.y, l2 + ev.z, l3 + ev.w);
                    atomicAdd(aggrow + col + 0, l0);
                    atomicAdd(aggrow + col + 1, l1);
                    atomicAdd(aggrow + col + 2, l2);
                    atomicAdd(aggrow + col + 3, l3);
                }
            }
        }
        TC_FENCE_BEFORE();
    }
    __syncthreads();
    if (tid == 0) MBAR_INVAL(mbar);
    __syncthreads();
    if (wid == 0) TC_DEALLOC(dT, 512);
#else
    // ---------- fallback (generic arch): two 64-row halves, R1 algorithm ----------
    float* sIn = (float*)smraw;              // 64*384
    float* sW  = sIn + FB_TM * 384;          // 16*128
    float* sB  = sW + 16 * HD;               // 64*128
    float* sA  = sIn;
    int tid = threadIdx.x, tx = tid & 31, ty = tid >> 5;

    for (int h64 = 0; h64 < 2; h64++) {
        long base = (long)blockIdx.x * MT + h64 * FB_TM;
        __syncthreads();
        for (int task = ty; task < FB_TM * 3; task += 8) {
            int rr = task / 3, sgm = task - rr * 3;
            long e = base + rr; if (e >= E) e = E - 1;
            const float* src;
            if (sgm == 0)      src = node_attr + (size_t)senders[e] * HD;
            else if (sgm == 1) src = node_attr + (size_t)receivers[e] * HD;
            else               src = edge_attr + (size_t)e * HD;
            ((float4*)(sIn + rr * 384 + sgm * HD))[tx] = ((const float4*)src)[tx];
        }
        fb_gemm(w0, eb0, sIn, 384, sW, sB, 384, true,  tid, tx, ty);
        fb_gemm(w1, eb1, sB,  HD,  sW, sA, HD,  true,  tid, tx, ty);
        fb_gemm(w2, eb2, sA,  HD,  sW, sB, HD,  true,  tid, tx, ty);
        fb_gemm(w3, eb3, sB,  HD,  sW, sA, HD,  false, tid, tx, ty);
        __syncthreads();

        int rr = tid >> 2, seg = tid & 3;
        const float* row = sA + rr * HD + seg * 32;
        float s = 0.f, s2 = 0.f;
#pragma unroll
        for (int i = 0; i < 32; i++) { float x = row[i]; s += x; s2 = fmaf(x, x, s2); }
        s  += __shfl_xor_sync(0xffffffffu, s, 1);
        s  += __shfl_xor_sync(0xffffffffu, s, 2);
        s2 += __shfl_xor_sync(0xffffffffu, s2, 1);
        s2 += __shfl_xor_sync(0xffffffffu, s2, 2);
        float m   = s * (1.0f / HD);
        float var = fmaxf(s2 * (1.0f / HD) - m * m, 0.f);
        float rs  = rsqrtf(var + 1e-5f);

        long e = base + rr;
        if (e < E) {
            int rv = receivers[e];
            float* aggrow = g_agg + (size_t)rv * HD;
            const float4* ea4 = (const float4*)(edge_attr + (size_t)e * HD);
            float4* oe4 = (float4*)(out_edge + (size_t)e * HD);
#pragma unroll
            for (int q = 0; q < 8; q++) {
                int h = seg * 32 + q * 4;
                float4 x4 = *(const float4*)(row + q * 4);
                float4 g4 = *(const float4*)(eg + h);
                float4 t4 = *(const float4*)(ebt + h);
                float4 ln;
                ln.x = (x4.x - m) * rs * g4.x + t4.x;
                ln.y = (x4.y - m) * rs * g4.y + t4.y;
                ln.z = (x4.z - m) * rs * g4.z + t4.z;
                ln.w = (x4.w - m) * rs * g4.w + t4.w;
                float4 eav = ea4[seg * 8 + q];
                oe4[seg * 8 + q] = make_float4(ln.x + eav.x, ln.y + eav.y,
                                               ln.z + eav.z, ln.w + eav.w);
                atomicAdd(aggrow + h + 0, ln.x);
                atomicAdd(aggrow + h + 1, ln.y);
                atomicAdd(aggrow + h + 2, ln.z);
                atomicAdd(aggrow + h + 3, ln.w);
            }
        }
        __syncthreads();
    }
#endif
}

// ---------------- node kernel ----------------
__global__ void __launch_bounds__(NT, 1) __cluster_dims__(1, 1, 1) node_kernel(
    const float* __restrict__ node_attr,
    const float* __restrict__ w0, const float* __restrict__ w1,
    const float* __restrict__ w2, const float* __restrict__ w3,
    const float* __restrict__ nb0, const float* __restrict__ nb1,
    const float* __restrict__ nb2, const float* __restrict__ nb3,
    const float* __restrict__ ng, const float* __restrict__ nbt,
    float* __restrict__ out_node, int N)
{
    extern __shared__ uint8_t smraw[];
#if HAS_TC
    uint32_t sb = smem_u32(smraw);
    uint32_t sbase = (sb + 1023) & ~1023u;
    uint8_t* sm = smraw + (sbase - sb);
    float* sBias = (float*)(sm + OFF_BIAS);
    float* sG    = (float*)(sm + OFF_G);
    float* sBt   = (float*)(sm + OFF_BT);
    uint32_t* sTm = (uint32_t*)(sm + OFF_TM);
    uint32_t mbar = sbase + OFF_MBAR;

    int tid = threadIdx.x;
    int wid = tid >> 5;
    bool wg0 = (wid < 4);
    int wg_tid = tid & 127;
    uint32_t woff = ((uint32_t)(wg_tid >> 5)) << 21;
    long base = (long)blockIdx.x * MT;
    long n = base + wg_tid;
    long nc = (n < N) ? n : (long)(N - 1);

    if (wid == 0) TC_ALLOC(sbase + OFF_TM, 512);
    else TC_RELINQ();
    if (tid == 0) MBAR_INIT(mbar, 1);
    if (tid < 128) {
        sBias[tid] = nb0[tid]; sBias[128 + tid] = nb1[tid];
        sBias[256 + tid] = nb2[tid]; sBias[384 + tid] = nb3[tid];
        sG[tid] = ng[tid]; sBt[tid] = nbt[tid];
    }
    __syncthreads();
    uint32_t dT = *sTm;

    int phase = 0;
    for (int step = 0; step < 5; step++) {
        if (wg0) {
            if (step < 2) {
                const float* src = (step == 0) ? node_attr + (size_t)nc * HD
                                               : g_agg + (size_t)nc * HD;
                gm_row_to_A(src, dT, woff);
            } else {
                d_row_to_A(dT, sBias + (step - 2) * 128, woff);
            }
            TC_FENCE_BEFORE();
        } else {
            copy_wimg(6 + step, (uint4*)(sm + OFF_W), wg_tid);
            FENCE_ASYNC();
        }
        __syncthreads();
        if (wid == 0) {
            if (elect1()) {
                TC_FENCE_AFTER();
                dispatch_mma(dT, sbase + OFF_W, (step == 0 || step >= 2));
                TC_COMMIT(mbar);
            }
        }
        MBAR_WAIT(mbar, phase);
        phase ^= 1;
        TC_FENCE_AFTER();
    }

    if (wg0) {
        float s = 0.f, s2 = 0.f;
#pragma unroll
        for (int c = 0; c < 4; c++) {
            uint32_t d[32];
            LD32(d, dT + D_COL + c * 32 + woff);
            TC_WAIT_LD();
#pragma unroll
            for (int i = 0; i < 32; i++) {
                float x = __uint_as_float(d[i]) + sBias[384 + c * 32 + i];
                s += x; s2 = fmaf(x, x, s2);
            }
        }
        float m   = s * (1.0f / HD);
        float var = fmaxf(s2 * (1.0f / HD) - m * m, 0.f);
        float rs  = rsqrtf(var + 1e-5f);

        const float* na = node_attr + (size_t)nc * HD;
        float* on = out_node + (size_t)nc * HD;

#pragma unroll
        for (int c = 0; c < 4; c++) {
            uint32_t d[32];
            LD32(d, dT + D_COL + c * 32 + woff);
            TC_WAIT_LD();
            if (n < N) {
#pragma unroll
                for (int g = 0; g < 8; g++) {
                    int col = c * 32 + g * 4;
                    float4 nv = *(const float4*)(na + col);
                    float4 ov;
                    ov.x = (__uint_as_float(d[g*4+0]) + sBias[384+col+0] - m) * rs * sG[col+0] + sBt[col+0] + nv.x;
                    ov.y = (__uint_as_float(d[g*4+1]) + sBias[384+col+1] - m) * rs * sG[col+1] + sBt[col+1] + nv.y;
                    ov.z = (__uint_as_float(d[g*4+2]) + sBias[384+col+2] - m) * rs * sG[col+2] + sBt[col+2] + nv.z;
                    ov.w = (__uint_as_float(d[g*4+3]) + sBias[384+col+3] - m) * rs * sG[col+3] + sBt[col+3] + nv.w;
                    *(float4*)(on + col) = ov;
                }
            }
        }
        TC_FENCE_BEFORE();
    }
    __syncthreads();
    if (tid == 0) MBAR_INVAL(mbar);
    __syncthreads();
    if (wid == 0) TC_DEALLOC(dT, 512);
#else
    // ---------- fallback ----------
    float* sIn = (float*)smraw;              // 64*256
    float* sW  = sIn + FB_TM * 256;          // 16*128
    float* sB  = sW + 16 * HD;               // 64*128
    float* sA  = sIn;
    int tid = threadIdx.x, tx = tid & 31, ty = tid >> 5;

    for (int h64 = 0; h64 < 2; h64++) {
        long base = (long)blockIdx.x * MT + h64 * FB_TM;
        __syncthreads();
        for (int task = ty; task < FB_TM * 2; task += 8) {
            int rr = task >> 1, sgm = task & 1;
            long n = base + rr; if (n >= N) n = N - 1;
            const float* src = (sgm == 0) ? node_attr + (size_t)n * HD
                                          : g_agg + (size_t)n * HD;
            ((float4*)(sIn + rr * 256 + sgm * HD))[tx] = ((const float4*)src)[tx];
        }
        fb_gemm(w0, nb0, sIn, 256, sW, sB, 256, true,  tid, tx, ty);
        fb_gemm(w1, nb1, sB,  HD,  sW, sA, HD,  true,  tid, tx, ty);
        fb_gemm(w2, nb2, sA,  HD,  sW, sB, HD,  true,  tid, tx, ty);
        fb_gemm(w3, nb3, sB,  HD,  sW, sA, HD,  false, tid, tx, ty);
        __syncthreads();

        int rr = tid >> 2, seg = tid & 3;
        const float* row = sA + rr * HD + seg * 32;
        float s = 0.f, s2 = 0.f;
#pragma unroll
        for (int i = 0; i < 32; i++) { float x = row[i]; s += x; s2 = fmaf(x, x, s2); }
        s  += __shfl_xor_sync(0xffffffffu, s, 1);
        s  += __shfl_xor_sync(0xffffffffu, s, 2);
        s2 += __shfl_xor_sync(0xffffffffu, s2, 1);
        s2 += __shfl_xor_sync(0xffffffffu, s2, 2);
        float m   = s * (1.0f / HD);
        float var = fmaxf(s2 * (1.0f / HD) - m * m, 0.f);
        float rs  = rsqrtf(var + 1e-5f);

        long n = base + rr;
        if (n < N) {
            const float4* na4 = (const float4*)(node_attr + (size_t)n * HD);
            float4* on4 = (float4*)(out_node + (size_t)n * HD);
#pragma unroll
            for (int q = 0; q < 8; q++) {
                int h = seg * 32 + q * 4;
                float4 x4 = *(const float4*)(row + q * 4);
                float4 g4 = *(const float4*)(ng + h);
                float4 t4 = *(const float4*)(nbt + h);
                float4 nav = na4[seg * 8 + q];
                float4 ov;
                ov.x = (x4.x - m) * rs * g4.x + t4.x + nav.x;
                ov.y = (x4.y - m) * rs * g4.y + t4.y + nav.y;
                ov.z = (x4.z - m) * rs * g4.z + t4.z + nav.z;
                ov.w = (x4.w - m) * rs * g4.w + t4.w + nav.w;
                on4[seg * 8 + q] = ov;
            }
        }
        __syncthreads();
    }
#endif
}

// ---------------- launch ----------------
extern "C" void kernel_launch(void* const* d_in, const int* in_sizes, int n_in,
                              void* d_out, int out_size)
{
    const float* node_attr = (const float*)d_in[0];
    const float* edge_attr = (const float*)d_in[1];
    const int*   ei        = (const int*)d_in[2];
    const float* ew0 = (const float*)d_in[4];  const float* eb0 = (const float*)d_in[5];
    const float* ew1 = (const float*)d_in[6];  const float* eb1 = (const float*)d_in[7];
    const float* ew2 = (const float*)d_in[8];  const float* eb2 = (const float*)d_in[9];
    const float* ew3 = (const float*)d_in[10]; const float* eb3 = (const float*)d_in[11];
    const float* eg  = (const float*)d_in[12]; const float* ebt = (const float*)d_in[13];
    const float* nw0 = (const float*)d_in[14]; const float* nb0 = (const float*)d_in[15];
    const float* nw1 = (const float*)d_in[16]; const float* nb1 = (const float*)d_in[17];
    const float* nw2 = (const float*)d_in[18]; const float* nb2 = (const float*)d_in[19];
    const float* nw3 = (const float*)d_in[20]; const float* nb3 = (const float*)d_in[21];
    const float* ng  = (const float*)d_in[22]; const float* nbt = (const float*)d_in[23];

    int N = in_sizes[0] / HD;
    int E = in_sizes[1] / HD;

    float* out_node = (float*)d_out;
    float* out_edge = out_node + (size_t)N * HD;

    cudaFuncSetAttribute(edge_kernel, cudaFuncAttributeMaxDynamicSharedMemorySize, SMEM_SZ);
    cudaFuncSetAttribute(node_kernel, cudaFuncAttributeMaxDynamicSharedMemorySize, SMEM_SZ);

    zero_agg_kernel<<<1024, 256>>>(N * HD / 4);

    // weight images: 0-2 ew0 slices, 3-5 ew1..3, 6-7 nw0 slices, 8-10 nw1..3
    prep_w_kernel<<<64, 256>>>(ew0, 0, 0);
    prep_w_kernel<<<64, 256>>>(ew0, 128, 1);
    prep_w_kernel<<<64, 256>>>(ew0, 256, 2);
    prep_w_kernel<<<64, 256>>>(ew1, 0, 3);
    prep_w_kernel<<<64, 256>>>(ew2, 0, 4);
    prep_w_kernel<<<64, 256>>>(ew3, 0, 5);
    prep_w_kernel<<<64, 256>>>(nw0, 0, 6);
    prep_w_kernel<<<64, 256>>>(nw0, 128, 7);
    prep_w_kernel<<<64, 256>>>(nw1, 0, 8);
    prep_w_kernel<<<64, 256>>>(nw2, 0, 9);
    prep_w_kernel<<<64, 256>>>(nw3, 0, 10);

    const int* senders   = ei;
    const int* receivers = ei + E;

    edge_kernel<<<(E + MT - 1) / MT, NT, SMEM_SZ>>>(
        node_attr, edge_attr, senders, receivers,
        ew0, ew1, ew2, ew3,
        eb0, eb1, eb2, eb3, eg, ebt, out_edge, E);

    node_kernel<<<(N + MT - 1) / MT, NT, SMEM_SZ>>>(
        node_attr,
        nw0, nw1, nw2, nw3,
        nb0, nb1, nb2, nb3, ng, nbt, out_node, N);
}

// round 12
// speedup vs baseline: 3.2108x; 1.0131x over previous
#include <cuda_runtime.h>
#include <cstdint>

#define HD 128
#define MT 128
#define NT 256
#define MAXN 100000

#if !defined(__CUDA_ARCH__) || defined(__CUDA_ARCH_FEAT_SM103_ALL)
#define HAS_TC 1
#else
#define HAS_TC 0
#endif

__device__ float g_agg[(size_t)MAXN * HD];
__device__ unsigned char g_wimg[11 * 65536];

// ---------------- helpers ----------------
__device__ __forceinline__ uint32_t smem_u32(const void* p) {
    uint32_t a;
    asm("{ .reg .u64 t; cvta.to.shared.u64 t, %1; cvt.u32.u64 %0, t; }" : "=r"(a) : "l"(p));
    return a;
}

#if HAS_TC
__device__ __forceinline__ uint32_t elect1() {
    uint32_t p;
    asm volatile("{ .reg .pred p; elect.sync _|p, 0xFFFFFFFF; selp.b32 %0, 1, 0, p; }" : "=r"(p));
    return p;
}

#define TC_ALLOC(slot, n) asm volatile("tcgen05.alloc.cta_group::1.sync.aligned.shared::cta.b32 [%0], %1;" :: "r"(slot), "r"(n) : "memory")
#define TC_RELINQ()       asm volatile("tcgen05.relinquish_alloc_permit.cta_group::1.sync.aligned;")
#define TC_DEALLOC(t, n)  asm volatile("tcgen05.dealloc.cta_group::1.sync.aligned.b32 %0, %1;" :: "r"(t), "r"(n))
#define TC_COMMIT(mb)     asm volatile("tcgen05.commit.cta_group::1.mbarrier::arrive::one.shared::cluster.b64 [%0];" :: "r"(mb) : "memory")
#define TC_WAIT_LD()      asm volatile("tcgen05.wait::ld.sync.aligned;" ::: "memory")
#define TC_WAIT_ST()      asm volatile("tcgen05.wait::st.sync.aligned;" ::: "memory")
#define TC_FENCE_BEFORE() asm volatile("tcgen05.fence::before_thread_sync;" ::: "memory")
#define TC_FENCE_AFTER()  asm volatile("tcgen05.fence::after_thread_sync;" ::: "memory")
#define FENCE_ASYNC()     asm volatile("fence.proxy.async.shared::cta;" ::: "memory")
#define MBAR_INIT(mb, c)  asm volatile("mbarrier.init.shared.b64 [%0], %1;" :: "r"(mb), "r"(c) : "memory")
#define MBAR_INVAL(mb)    asm volatile("mbarrier.inval.shared.b64 [%0];" :: "r"(mb) : "memory")

#define MBAR_WAIT(mbar, phase) do { \
    uint32_t _mb = (mbar), _ph = (phase), _done; \
    asm volatile("{\n\t.reg .pred p;\n\t" \
        "mbarrier.try_wait.parity.acquire.cta.shared::cta.b64 p, [%1], %2;\n\t" \
        "selp.b32 %0, 1, 0, p;\n\t}" : "=r"(_done) : "r"(_mb), "r"(_ph) : "memory"); \
    if (!_done) { \
        asm volatile("{\n\t.reg .pred P1;\n\t" \
            "WL_%=:\n\t" \
            "mbarrier.try_wait.parity.acquire.cta.shared::cta.b64 P1, [%0], %1, 0x989680;\n\t" \
            "@P1 bra.uni WD_%=;\n\t" \
            "bra.uni WL_%=;\n\t" \
            "WD_%=:\n\t}" :: "r"(_mb), "r"(_ph) : "memory"); \
    } \
} while (0)

#define LD32(r, addr) \
    asm volatile("tcgen05.ld.sync.aligned.32x32b.x32.b32 " \
        "{%0, %1, %2, %3, %4, %5, %6, %7, " \
        " %8, %9, %10, %11, %12, %13, %14, %15, " \
        " %16, %17, %18, %19, %20, %21, %22, %23, " \
        " %24, %25, %26, %27, %28, %29, %30, %31}, [%32];" \
        : "=r"((r)[0]),  "=r"((r)[1]),  "=r"((r)[2]),  "=r"((r)[3]), \
          "=r"((r)[4]),  "=r"((r)[5]),  "=r"((r)[6]),  "=r"((r)[7]), \
          "=r"((r)[8]),  "=r"((r)[9]),  "=r"((r)[10]), "=r"((r)[11]), \
          "=r"((r)[12]), "=r"((r)[13]), "=r"((r)[14]), "=r"((r)[15]), \
          "=r"((r)[16]), "=r"((r)[17]), "=r"((r)[18]), "=r"((r)[19]), \
          "=r"((r)[20]), "=r"((r)[21]), "=r"((r)[22]), "=r"((r)[23]), \
          "=r"((r)[24]), "=r"((r)[25]), "=r"((r)[26]), "=r"((r)[27]), \
          "=r"((r)[28]), "=r"((r)[29]), "=r"((r)[30]), "=r"((r)[31]) \
        : "r"(addr))

#define ST16(addr, r) \
    asm volatile("tcgen05.st.sync.aligned.32x32b.x16.b32 [%0], " \
        "{%1, %2, %3, %4, %5, %6, %7, %8, " \
        " %9, %10, %11, %12, %13, %14, %15, %16};" \
        :: "r"(addr), \
           "r"((r)[0]),  "r"((r)[1]),  "r"((r)[2]),  "r"((r)[3]), \
           "r"((r)[4]),  "r"((r)[5]),  "r"((r)[6]),  "r"((r)[7]), \
           "r"((r)[8]),  "r"((r)[9]),  "r"((r)[10]), "r"((r)[11]), \
           "r"((r)[12]), "r"((r)[13]), "r"((r)[14]), "r"((r)[15]) \
        : "memory")
#endif  // HAS_TC

// test_mma_iter B layout: N=32 tile, K=128, blocked atoms (4 atom-rows x 2 atom-cols)
__device__ __host__ __forceinline__ uint32_t b_off32(int row, int col) {
    uint32_t off = ((uint32_t)(row >> 3) + (uint32_t)(col >> 6) * 4u) * 1024u
                 + (uint32_t)(row & 7) * 128u + (uint32_t)(col & 63) * 2u;
    return off ^ ((off >> 3) & 0x70u);
}

__device__ __forceinline__ uint64_t mk_desc(uint32_t a) {
    return ((uint64_t)2 << 61) | ((uint64_t)1 << 46) | ((uint64_t)64 << 32)
         | ((uint64_t)1 << 16) | ((uint64_t)(a >> 4) & 0x3FFF);
}

// ---------------- weight prep (arch-generic, ONE merged launch) ----------------
__global__ void prep_w_all_kernel(
    const float* __restrict__ ew0, const float* __restrict__ ew1,
    const float* __restrict__ ew2, const float* __restrict__ ew3,
    const float* __restrict__ nw0, const float* __restrict__ nw1,
    const float* __restrict__ nw2, const float* __restrict__ nw3)
{
    int img = blockIdx.y;
    const float* W;
    int kbase;
    switch (img) {
        case 0:  W = ew0; kbase = 0;   break;
        case 1:  W = ew0; kbase = 128; break;
        case 2:  W = ew0; kbase = 256; break;
        case 3:  W = ew1; kbase = 0;   break;
        case 4:  W = ew2; kbase = 0;   break;
        case 5:  W = ew3; kbase = 0;   break;
        case 6:  W = nw0; kbase = 0;   break;
        case 7:  W = nw0; kbase = 128; break;
        case 8:  W = nw1; kbase = 0;   break;
        case 9:  W = nw2; kbase = 0;   break;
        default: W = nw3; kbase = 0;   break;
    }
    int idx = blockIdx.x * blockDim.x + threadIdx.x;
    if (idx >= 128 * 128) return;
    int n = idx >> 7, k = idx & 127;
    float x = W[(size_t)(kbase + k) * HD + n];
    uint32_t xb = __float_as_uint(x);
    uint32_t hb = (xb + 0x7FFFu + ((xb >> 16) & 1u)) & 0xFFFF0000u;
    float lo = x - __uint_as_float(hb);
    uint32_t lb = __float_as_uint(lo);
    uint32_t l16 = ((lb + 0x7FFFu + ((lb >> 16) & 1u)) >> 16) & 0xFFFFu;
    int tile = n >> 5, r32 = n & 31;
    uint32_t off = b_off32(r32, k);
    unsigned char* base = g_wimg + (size_t)img * 65536 + (size_t)tile * 8192;
    *(uint16_t*)(base + off)         = (uint16_t)(hb >> 16);
    *(uint16_t*)(base + 32768 + off) = (uint16_t)l16;
}

__global__ void zero_agg_kernel(int n4) {
    int i = blockIdx.x * blockDim.x + threadIdx.x;
    float4 z = make_float4(0.f, 0.f, 0.f, 0.f);
    for (; i < n4; i += gridDim.x * blockDim.x)
        ((float4*)g_agg)[i] = z;
}

#if HAS_TC
// ---------------- tcgen05 device pieces (EXACT R6) ----------------
// TMEM columns: A_hi 0-63, A_lo 64-127, D 128-255.
#define A_LO_COL 64
#define D_COL    128
#define TM_COLS  512

__device__ __forceinline__ void split2(float x0, float x1, uint32_t& h, uint32_t& l) {
    uint32_t b0 = __float_as_uint(x0), b1 = __float_as_uint(x1);
    uint32_t h0 = (b0 + 0x7FFFu + ((b0 >> 16) & 1u)) & 0xFFFF0000u;
    uint32_t h1 = (b1 + 0x7FFFu + ((b1 >> 16) & 1u)) & 0xFFFF0000u;
    h = (h0 >> 16) | h1;
    float l0 = x0 - __uint_as_float(h0);
    float l1 = x1 - __uint_as_float(h1);
    asm("cvt.rn.bf16x2.f32 %0, %1, %2;" : "=r"(l) : "f"(l1), "f"(l0));
}

__device__ __forceinline__ void gm_row_to_A(const float* p, uint32_t dT, uint32_t woff) {
#pragma unroll
    for (int c = 0; c < 4; c++) {
        uint32_t hi[16], lo[16];
#pragma unroll
        for (int i = 0; i < 8; i++) {
            float4 v = ((const float4*)p)[c * 8 + i];
            split2(v.x, v.y, hi[2 * i], lo[2 * i]);
            split2(v.z, v.w, hi[2 * i + 1], lo[2 * i + 1]);
        }
        ST16(dT + c * 16 + woff, hi);
        ST16(dT + A_LO_COL + c * 16 + woff, lo);
    }
    TC_WAIT_ST();
}

__device__ __forceinline__ void d_row_to_A(uint32_t dT, const float* bias, uint32_t woff) {
#pragma unroll
    for (int c = 0; c < 4; c++) {
        uint32_t d[32];
        LD32(d, dT + D_COL + c * 32 + woff);
        TC_WAIT_LD();
        uint32_t hi[16], lo[16];
#pragma unroll
        for (int m = 0; m < 16; m++) {
            float x0 = fmaxf(__uint_as_float(d[2 * m]) + bias[c * 32 + 2 * m], 0.f);
            float x1 = fmaxf(__uint_as_float(d[2 * m + 1]) + bias[c * 32 + 2 * m + 1], 0.f);
            split2(x0, x1, hi[m], lo[m]);
        }
        ST16(dT + c * 16 + woff, hi);
        ST16(dT + A_LO_COL + c * 16 + woff, lo);
    }
    TC_WAIT_ST();
}

__device__ __forceinline__ void copy_wimg(int img, uint4* wdst, int wtid) {
    const uint4* src = (const uint4*)(g_wimg + (size_t)img * 65536);
#pragma unroll
    for (int it = 0; it < 32; it++) {
        int t = wtid + it * 128;
        wdst[t] = src[t];
    }
}

// 96 dispatches: 4 N=32 tiles x 3 split terms x 8 K=16 steps. R6-proven TS form.
__device__ __forceinline__ void dispatch_mma(uint32_t dT, uint32_t wsm, bool first) {
    const uint32_t idesc = 0x8080490u;
    uint32_t z = 0;
#pragma unroll
    for (int tile = 0; tile < 4; tile++) {
        uint32_t d = dT + D_COL + tile * 32;
#pragma unroll
        for (int term = 0; term < 3; term++) {
            uint32_t a_base = dT + (term == 1 ? A_LO_COL : 0);
            uint64_t bd = mk_desc(wsm + (term == 2 ? 32768u : 0u) + tile * 8192u);
#pragma unroll
            for (int ks = 0; ks < 8; ks++) {
                uint32_t a = a_base + ks * 8;
                uint64_t b = bd + (uint64_t)((ks & 3) * 2 + (ks >> 2) * 256);
                uint32_t en = (first && term == 0 && ks == 0) ? 0u : 1u;
                asm volatile("{\n\t.reg .pred p;\n\tsetp.ne.u32 p, %5, 0;\n\t"
                    "tcgen05.mma.cta_group::1.kind::f16 [%0], [%1], %2, %3, {%4, %4, %4, %4}, p;\n\t}"
                    :: "r"(d), "r"(a), "l"(b), "r"(idesc), "r"(z), "r"(en)
                    : "memory");
            }
        }
    }
}
#endif  // HAS_TC

// smem layout (1024-aligned base) — EXACT R6
#define OFF_W    0
#define OFF_BIAS 65536
#define OFF_G    67584
#define OFF_BT   68096
#define OFF_TM   68608
#define OFF_MBAR 68616
#define SMEM_SZ  139264

// ---------------- edge kernel (EXACT R6) ----------------
__global__ void __launch_bounds__(NT, 1) __cluster_dims__(1, 1, 1) edge_kernel(
    const float* __restrict__ node_attr, const float* __restrict__ edge_attr,
    const int* __restrict__ senders, const int* __restrict__ receivers,
    const float* __restrict__ w0, const float* __restrict__ w1,
    const float* __restrict__ w2, const float* __restrict__ w3,
    const float* __restrict__ eb0, const float* __restrict__ eb1,
    const float* __restrict__ eb2, const float* __restrict__ eb3,
    const float* __restrict__ eg, const float* __restrict__ ebt,
    float* __restrict__ out_edge, int E)
{
    extern __shared__ uint8_t smraw[];
#if HAS_TC
    uint32_t sb = smem_u32(smraw);
    uint32_t sbase = (sb + 1023) & ~1023u;
    uint8_t* sm = smraw + (sbase - sb);
    float* sBias = (float*)(sm + OFF_BIAS);
    float* sG    = (float*)(sm + OFF_G);
    float* sBt   = (float*)(sm + OFF_BT);
    uint32_t* sTm = (uint32_t*)(sm + OFF_TM);
    uint32_t mbar = sbase + OFF_MBAR;

    int tid = threadIdx.x;
    int wid = tid >> 5;
    bool wg0 = (wid < 4);
    int wg_tid = tid & 127;
    uint32_t woff = ((uint32_t)(wg_tid >> 5)) << 21;
    long base = (long)blockIdx.x * MT;
    long e = base + wg_tid;
    long ec = (e < E) ? e : (long)(E - 1);

    if (wid == 0) TC_ALLOC(sbase + OFF_TM, TM_COLS);
    else TC_RELINQ();
    if (tid == 0) MBAR_INIT(mbar, 1);
    if (tid < 128) {
        sBias[tid] = eb0[tid]; sBias[128 + tid] = eb1[tid];
        sBias[256 + tid] = eb2[tid]; sBias[384 + tid] = eb3[tid];
        sG[tid] = eg[tid]; sBt[tid] = ebt[tid];
    }
    __syncthreads();
    uint32_t dT = *sTm;

    int phase = 0;
    for (int step = 0; step < 6; step++) {
        if (wg0) {
            if (step < 3) {
                const float* src;
                if (step == 0)      src = node_attr + (size_t)senders[ec] * HD;
                else if (step == 1) src = node_attr + (size_t)receivers[ec] * HD;
                else                src = edge_attr + (size_t)ec * HD;
                gm_row_to_A(src, dT, woff);
            } else {
                d_row_to_A(dT, sBias + (step - 3) * 128, woff);
            }
            TC_FENCE_BEFORE();
        } else {
            copy_wimg(step, (uint4*)(sm + OFF_W), wg_tid);
            FENCE_ASYNC();
        }
        __syncthreads();
        if (wid == 0) {
            if (elect1()) {
                TC_FENCE_AFTER();
                dispatch_mma(dT, sbase + OFF_W, (step == 0 || step >= 3));
                TC_COMMIT(mbar);
            }
        }
        MBAR_WAIT(mbar, phase);
        phase ^= 1;
        TC_FENCE_AFTER();
    }

    // ---- LayerNorm + residual + scatter (WG0 only) ----
    if (wg0) {
        float s = 0.f, s2 = 0.f;
#pragma unroll
        for (int c = 0; c < 4; c++) {
            uint32_t d[32];
            LD32(d, dT + D_COL + c * 32 + woff);
            TC_WAIT_LD();
#pragma unroll
            for (int i = 0; i < 32; i++) {
                float x = __uint_as_float(d[i]) + sBias[384 + c * 32 + i];
                s += x; s2 = fmaf(x, x, s2);
            }
        }
        float m   = s * (1.0f / HD);
        float var = fmaxf(s2 * (1.0f / HD) - m * m, 0.f);
        float rs  = rsqrtf(var + 1e-5f);

        int rv = (e < E) ? receivers[e] : 0;
        const float* ea = edge_attr + (size_t)ec * HD;
        float* oe = out_edge + (size_t)ec * HD;
        float* aggrow = g_agg + (size_t)rv * HD;

#pragma unroll
        for (int c = 0; c < 4; c++) {
            uint32_t d[32];
            LD32(d, dT + D_COL + c * 32 + woff);
            TC_WAIT_LD();
            if (e < E) {
#pragma unroll
                for (int g = 0; g < 8; g++) {
                    int col = c * 32 + g * 4;
                    float l0 = (__uint_as_float(d[g*4+0]) + sBias[384+col+0] - m) * rs * sG[col+0] + sBt[col+0];
                    float l1 = (__uint_as_float(d[g*4+1]) + sBias[384+col+1] - m) * rs * sG[col+1] + sBt[col+1];
                    float l2 = (__uint_as_float(d[g*4+2]) + sBias[384+col+2] - m) * rs * sG[col+2] + sBt[col+2];
                    float l3 = (__uint_as_float(d[g*4+3]) + sBias[384+col+3] - m) * rs * sG[col+3] + sBt[col+3];
                    float4 ev = *(const float4*)(ea + col);
                    float4 ov = make_float4(l0 + ev.x, l1 + ev.y, l2 + ev.z, l3 + ev.w);
                    *(float4*)(oe + col) = ov;
                    atomicAdd(aggrow + col + 0, l0);
                    atomicAdd(aggrow + col + 1, l1);
                    atomicAdd(aggrow + col + 2, l2);
                    atomicAdd(aggrow + col + 3, l3);
                }
            }
        }
        TC_FENCE_BEFORE();
    }
    __syncthreads();
    if (tid == 0) MBAR_INVAL(mbar);
    __syncthreads();
    if (wid == 0) TC_DEALLOC(dT, TM_COLS);
#else
    // ---------- naive fallback (never executes on sm_103a; compile-only) ----------
    int tid = threadIdx.x;
    if (tid < 128) {
        long e = (long)blockIdx.x * MT + tid;
        if (e < E) {
            float x[384], h0[128], h1[128];
            const float* sa = node_attr + (size_t)senders[e] * HD;
            const float* ra = node_attr + (size_t)receivers[e] * HD;
            const float* ea = edge_attr + (size_t)e * HD;
            for (int i = 0; i < 128; i++) { x[i] = sa[i]; x[128 + i] = ra[i]; x[256 + i] = ea[i]; }
            for (int o = 0; o < 128; o++) {
                float acc = eb0[o];
                for (int k = 0; k < 384; k++) acc += x[k] * w0[k * HD + o];
                h0[o] = fmaxf(acc, 0.f);
            }
            for (int o = 0; o < 128; o++) {
                float acc = eb1[o];
                for (int k = 0; k < 128; k++) acc += h0[k] * w1[k * HD + o];
                h1[o] = fmaxf(acc, 0.f);
            }
            for (int o = 0; o < 128; o++) {
                float acc = eb2[o];
                for (int k = 0; k < 128; k++) acc += h1[k] * w2[k * HD + o];
                h0[o] = fmaxf(acc, 0.f);
            }
            float s = 0.f, s2 = 0.f;
            for (int o = 0; o < 128; o++) {
                float acc = eb3[o];
                for (int k = 0; k < 128; k++) acc += h0[k] * w3[k * HD + o];
                h1[o] = acc; s += acc; s2 += acc * acc;
            }
            float m = s / HD, var = fmaxf(s2 / HD - m * m, 0.f);
            float rs = rsqrtf(var + 1e-5f);
            int rv = receivers[e];
            for (int o = 0; o < 128; o++) {
                float ln = (h1[o] - m) * rs * eg[o] + ebt[o];
                out_edge[(size_t)e * HD + o] = ln + ea[o];
                atomicAdd(g_agg + (size_t)rv * HD + o, ln);
            }
        }
    }
#endif
}

// ---------------- node kernel (EXACT R6) ----------------
__global__ void __launch_bounds__(NT, 1) __cluster_dims__(1, 1, 1) node_kernel(
    const float* __restrict__ node_attr,
    const float* __restrict__ w0, const float* __restrict__ w1,
    const float* __restrict__ w2, const float* __restrict__ w3,
    const float* __restrict__ nb0, const float* __restrict__ nb1,
    const float* __restrict__ nb2, const float* __restrict__ nb3,
    const float* __restrict__ ng, const float* __restrict__ nbt,
    float* __restrict__ out_node, int N)
{
    extern __shared__ uint8_t smraw[];
#if HAS_TC
    uint32_t sb = smem_u32(smraw);
    uint32_t sbase = (sb + 1023) & ~1023u;
    uint8_t* sm = smraw + (sbase - sb);
    float* sBias = (float*)(sm + OFF_BIAS);
    float* sG    = (float*)(sm + OFF_G);
    float* sBt   = (float*)(sm + OFF_BT);
    uint32_t* sTm = (uint32_t*)(sm + OFF_TM);
    uint32_t mbar = sbase + OFF_MBAR;

    int tid = threadIdx.x;
    int wid = tid >> 5;
    bool wg0 = (wid < 4);
    int wg_tid = tid & 127;
    uint32_t woff = ((uint32_t)(wg_tid >> 5)) << 21;
    long base = (long)blockIdx.x * MT;
    long n = base + wg_tid;
    long nc = (n < N) ? n : (long)(N - 1);

    if (wid == 0) TC_ALLOC(sbase + OFF_TM, TM_COLS);
    else TC_RELINQ();
    if (tid == 0) MBAR_INIT(mbar, 1);
    if (tid < 128) {
        sBias[tid] = nb0[tid]; sBias[128 + tid] = nb1[tid];
        sBias[256 + tid] = nb2[tid]; sBias[384 + tid] = nb3[tid];
        sG[tid] = ng[tid]; sBt[tid] = nbt[tid];
    }
    __syncthreads();
    uint32_t dT = *sTm;

    int phase = 0;
    for (int step = 0; step < 5; step++) {
        if (wg0) {
            if (step < 2) {
                const float* src = (step == 0) ? node_attr + (size_t)nc * HD
                                               : g_agg + (size_t)nc * HD;
                gm_row_to_A(src, dT, woff);
            } else {
                d_row_to_A(dT, sBias + (step - 2) * 128, woff);
            }
            TC_FENCE_BEFORE();
        } else {
            copy_wimg(6 + step, (uint4*)(sm + OFF_W), wg_tid);
            FENCE_ASYNC();
        }
        __syncthreads();
        if (wid == 0) {
            if (elect1()) {
                TC_FENCE_AFTER();
                dispatch_mma(dT, sbase + OFF_W, (step == 0 || step >= 2));
                TC_COMMIT(mbar);
            }
        }
        MBAR_WAIT(mbar, phase);
        phase ^= 1;
        TC_FENCE_AFTER();
    }

    if (wg0) {
        float s = 0.f, s2 = 0.f;
#pragma unroll
        for (int c = 0; c < 4; c++) {
            uint32_t d[32];
            LD32(d, dT + D_COL + c * 32 + woff);
            TC_WAIT_LD();
#pragma unroll
            for (int i = 0; i < 32; i++) {
                float x = __uint_as_float(d[i]) + sBias[384 + c * 32 + i];
                s += x; s2 = fmaf(x, x, s2);
            }
        }
        float m   = s * (1.0f / HD);
        float var = fmaxf(s2 * (1.0f / HD) - m * m, 0.f);
        float rs  = rsqrtf(var + 1e-5f);

        const float* na = node_attr + (size_t)nc * HD;
        float* on = out_node + (size_t)nc * HD;

#pragma unroll
        for (int c = 0; c < 4; c++) {
            uint32_t d[32];
            LD32(d, dT + D_COL + c * 32 + woff);
            TC_WAIT_LD();
            if (n < N) {
#pragma unroll
                for (int g = 0; g < 8; g++) {
                    int col = c * 32 + g * 4;
                    float4 nv = *(const float4*)(na + col);
                    float4 ov;
                    ov.x = (__uint_as_float(d[g*4+0]) + sBias[384+col+0] - m) * rs * sG[col+0] + sBt[col+0] + nv.x;
                    ov.y = (__uint_as_float(d[g*4+1]) + sBias[384+col+1] - m) * rs * sG[col+1] + sBt[col+1] + nv.y;
                    ov.z = (__uint_as_float(d[g*4+2]) + sBias[384+col+2] - m) * rs * sG[col+2] + sBt[col+2] + nv.z;
                    ov.w = (__uint_as_float(d[g*4+3]) + sBias[384+col+3] - m) * rs * sG[col+3] + sBt[col+3] + nv.w;
                    *(float4*)(on + col) = ov;
                }
            }
        }
        TC_FENCE_BEFORE();
    }
    __syncthreads();
    if (tid == 0) MBAR_INVAL(mbar);
    __syncthreads();
    if (wid == 0) TC_DEALLOC(dT, TM_COLS);
#else
    // ---------- naive fallback (never executes on sm_103a; compile-only) ----------
    int tid = threadIdx.x;
    if (tid < 128) {
        long nn = (long)blockIdx.x * MT + tid;
        if (nn < N) {
            float x[256], h0[128], h1[128];
            const float* na = node_attr + (size_t)nn * HD;
            const float* ag = g_agg + (size_t)nn * HD;
            for (int i = 0; i < 128; i++) { x[i] = na[i]; x[128 + i] = ag[i]; }
            for (int o = 0; o < 128; o++) {
                float acc = nb0[o];
                for (int k = 0; k < 256; k++) acc += x[k] * w0[k * HD + o];
                h0[o] = fmaxf(acc, 0.f);
            }
            for (int o = 0; o < 128; o++) {
                float acc = nb1[o];
                for (int k = 0; k < 128; k++) acc += h0[k] * w1[k * HD + o];
                h1[o] = fmaxf(acc, 0.f);
            }
            for (int o = 0; o < 128; o++) {
                float acc = nb2[o];
                for (int k = 0; k < 128; k++) acc += h1[k] * w2[k * HD + o];
                h0[o] = fmaxf(acc, 0.f);
            }
            float s = 0.f, s2 = 0.f;
            for (int o = 0; o < 128; o++) {
                float acc = nb3[o];
                for (int k = 0; k < 128; k++) acc += h0[k] * w3[k * HD + o];
                h1[o] = acc; s += acc; s2 += acc * acc;
            }
            float m = s / HD, var = fmaxf(s2 / HD - m * m, 0.f);
            float rs = rsqrtf(var + 1e-5f);
            for (int o = 0; o < 128; o++)
                out_node[(size_t)nn * HD + o] = (h1[o] - m) * rs * ng[o] + nbt[o] + na[o];
        }
    }
#endif
}

// ---------------- launch ----------------
extern "C" void kernel_launch(void* const* d_in, const int* in_sizes, int n_in,
                              void* d_out, int out_size)
{
    const float* node_attr = (const float*)d_in[0];
    const float* edge_attr = (const float*)d_in[1];
    const int*   ei        = (const int*)d_in[2];
    const float* ew0 = (const float*)d_in[4];  const float* eb0 = (const float*)d_in[5];
    const float* ew1 = (const float*)d_in[6];  const float* eb1 = (const float*)d_in[7];
    const float* ew2 = (const float*)d_in[8];  const float* eb2 = (const float*)d_in[9];
    const float* ew3 = (const float*)d_in[10]; const float* eb3 = (const float*)d_in[11];
    const float* eg  = (const float*)d_in[12]; const float* ebt = (const float*)d_in[13];
    const float* nw0 = (const float*)d_in[14]; const float* nb0 = (const float*)d_in[15];
    const float* nw1 = (const float*)d_in[16]; const float* nb1 = (const float*)d_in[17];
    const float* nw2 = (const float*)d_in[18]; const float* nb2 = (const float*)d_in[19];
    const float* nw3 = (const float*)d_in[20]; const float* nb3 = (const float*)d_in[21];
    const float* ng  = (const float*)d_in[22]; const float* nbt = (const float*)d_in[23];

    int N = in_sizes[0] / HD;
    int E = in_sizes[1] / HD;

    float* out_node = (float*)d_out;
    float* out_edge = out_node + (size_t)N * HD;

    cudaFuncSetAttribute(edge_kernel, cudaFuncAttributeMaxDynamicSharedMemorySize, SMEM_SZ);
    cudaFuncSetAttribute(node_kernel, cudaFuncAttributeMaxDynamicSharedMemorySize, SMEM_SZ);

    zero_agg_kernel<<<1024, 256>>>(N * HD / 4);

    // all 11 weight images in ONE launch (grid.y selects image) — host-only delta vs R6
    prep_w_all_kernel<<<dim3(64, 11), 256>>>(ew0, ew1, ew2, ew3, nw0, nw1, nw2, nw3);

    const int* senders   = ei;
    const int* receivers = ei + E;

    edge_kernel<<<(E + MT - 1) / MT, NT, SMEM_SZ>>>(
        node_attr, edge_attr, senders, receivers,
        ew0, ew1, ew2, ew3,
        eb0, eb1, eb2, eb3, eg, ebt, out_edge, E);

    node_kernel<<<(N + MT - 1) / MT, NT, SMEM_SZ>>>(
        node_attr,
        nw0, nw1, nw2, nw3,
        nb0, nb1, nb2, nb3, ng, nbt, out_node, N);
}